// round 2
// baseline (speedup 1.0000x reference)
#include <cuda_runtime.h>
#include <cuda_bf16.h>

#define N_NODES 50000
#define N_EDGES 800000
#define D 128

// Scratch aggregate buffer (no cudaMalloc allowed).
__device__ float g_agg[(size_t)N_NODES * D];

// ---------------------------------------------------------------------------
// Kernel 1: zero the aggregate buffer (float4 stores, grid-stride).
// ---------------------------------------------------------------------------
__global__ void zero_agg_kernel() {
    float4* p = reinterpret_cast<float4*>(g_agg);
    const int n4 = N_NODES * D / 4;
    for (int i = blockIdx.x * blockDim.x + threadIdx.x; i < n4;
         i += gridDim.x * blockDim.x) {
        p[i] = make_float4(0.f, 0.f, 0.f, 0.f);
    }
}

// ---------------------------------------------------------------------------
// Kernel 2: edge scatter. One warp per edge; each lane handles one float4
// (32 lanes x 16B = 512B = full feature row, coalesced gather).
// Scatter via red.global.add.v4.f32 -> single L2-side reduction per lane.
// Edge metadata staged through smem per block of 256 edges.
// ---------------------------------------------------------------------------
__global__ void scatter_kernel(const float* __restrict__ feature,
                               const int* __restrict__ edge_src,
                               const int* __restrict__ edge_dst,
                               const float* __restrict__ edge_w) {
    __shared__ int s_src[256];
    __shared__ int s_dst[256];
    __shared__ float s_w[256];

    const int base = blockIdx.x * 256;
    const int tid = threadIdx.x;
    const int e = base + tid;
    if (e < N_EDGES) {
        s_src[tid] = edge_src[e];
        s_dst[tid] = edge_dst[e];
        s_w[tid] = edge_w[e];
    }
    __syncthreads();

    const int warp = tid >> 5;
    const int lane = tid & 31;
    const int cnt = min(256, N_EDGES - base);

    for (int i = warp; i < cnt; i += 8) {
        const int s = s_src[i];
        const int d = s_dst[i];
        const float w = s_w[i];

        const float4 v =
            reinterpret_cast<const float4*>(feature + (size_t)s * D)[lane];
        const float x = v.x * w;
        const float y = v.y * w;
        const float z = v.z * w;
        const float u = v.w * w;

        float* dst = g_agg + (size_t)d * D + lane * 4;
        asm volatile("red.global.add.v4.f32 [%0], {%1, %2, %3, %4};"
                     :: "l"(dst), "f"(x), "f"(y), "f"(z), "f"(u)
                     : "memory");
    }
}

// ---------------------------------------------------------------------------
// Kernel 3: blended = 0.5*agg + 0.5*feature; out = blended @ W.
// 256 threads/block. W [128][129] (padded) in dynamic smem, loaded once per
// (persistent) block. 8 rows staged per iteration; each thread computes 4
// output elements (col j = tid&127, rows (tid>>7)*4 .. +3) for ILP.
// N_NODES = 50000 is divisible by 8 -> no row tail.
// ---------------------------------------------------------------------------
#define WS_PITCH (D + 1)

__global__ void gemm_kernel(const float* __restrict__ feature,
                            const float* __restrict__ weight,
                            float* __restrict__ out) {
    extern __shared__ float smem[];
    float* Ws = smem;                       // [D][WS_PITCH]
    float* rows = smem + D * WS_PITCH;      // [8][D]

    const int tid = threadIdx.x;

    // Stage W: Ws[k][j] = weight[k*D + j]
    for (int i = tid; i < D * D; i += 256) {
        Ws[(i / D) * WS_PITCH + (i % D)] = weight[i];
    }
    __syncthreads();

    const int j = tid & 127;
    const int rbase = (tid >> 7) * 4;   // 0 or 4

    for (int r0 = blockIdx.x * 8; r0 < N_NODES; r0 += gridDim.x * 8) {
        // Stage 8 blended rows (float4 loads).
        {
            const float4* fa = reinterpret_cast<const float4*>(feature + (size_t)r0 * D);
            const float4* ga = reinterpret_cast<const float4*>(g_agg + (size_t)r0 * D);
            float4* rw = reinterpret_cast<float4*>(rows);
            for (int i = tid; i < 8 * D / 4; i += 256) {
                float4 f = fa[i];
                float4 g = ga[i];
                rw[i] = make_float4(0.5f * (f.x + g.x), 0.5f * (f.y + g.y),
                                    0.5f * (f.z + g.z), 0.5f * (f.w + g.w));
            }
        }
        __syncthreads();

        float acc0 = 0.f, acc1 = 0.f, acc2 = 0.f, acc3 = 0.f;
        const float* r0p = rows + (rbase + 0) * D;
        const float* r1p = rows + (rbase + 1) * D;
        const float* r2p = rows + (rbase + 2) * D;
        const float* r3p = rows + (rbase + 3) * D;

        #pragma unroll 8
        for (int k = 0; k < D; k++) {
            const float wv = Ws[k * WS_PITCH + j];
            acc0 += r0p[k] * wv;
            acc1 += r1p[k] * wv;
            acc2 += r2p[k] * wv;
            acc3 += r3p[k] * wv;
        }

        out[(size_t)(r0 + rbase + 0) * D + j] = acc0;
        out[(size_t)(r0 + rbase + 1) * D + j] = acc1;
        out[(size_t)(r0 + rbase + 2) * D + j] = acc2;
        out[(size_t)(r0 + rbase + 3) * D + j] = acc3;
        __syncthreads();
    }
}

// ---------------------------------------------------------------------------
extern "C" void kernel_launch(void* const* d_in, const int* in_sizes, int n_in,
                              void* d_out, int out_size) {
    const float* feature  = (const float*)d_in[0];
    const int*   edge_src = (const int*)d_in[1];
    const int*   edge_dst = (const int*)d_in[2];
    const float* edge_w   = (const float*)d_in[3];
    const float* weight   = (const float*)d_in[4];
    float* out = (float*)d_out;

    (void)in_sizes; (void)n_in; (void)out_size;

    // GEMM needs >48KB dynamic smem.
    const int gemm_smem = (D * WS_PITCH + 8 * D) * (int)sizeof(float);
    static bool attr_set = false;
    if (!attr_set) {
        cudaFuncSetAttribute(gemm_kernel,
                             cudaFuncAttributeMaxDynamicSharedMemorySize,
                             gemm_smem);
        attr_set = true;
    }

    zero_agg_kernel<<<1184, 256>>>();
    scatter_kernel<<<(N_EDGES + 255) / 256, 256>>>(feature, edge_src, edge_dst,
                                                   edge_w);
    gemm_kernel<<<444, 256, gemm_smem>>>(feature, weight, out);
}

// round 3
// speedup vs baseline: 1.6719x; 1.6719x over previous
#include <cuda_runtime.h>
#include <cuda_bf16.h>

#define N_NODES 50000
#define N_EDGES 800000
#define D 128

// Scratch aggregate buffer (no cudaMalloc allowed).
__device__ float g_agg[(size_t)N_NODES * D];

typedef unsigned long long u64;

// ---------------------------------------------------------------------------
// f32x2 packed-FMA helpers (sm_103a; ptxas will not auto-fuse — PTX only).
// ---------------------------------------------------------------------------
__device__ __forceinline__ u64 pack2(float a, float b) {
    u64 r;
    asm("mov.b64 %0, {%1, %2};" : "=l"(r) : "f"(a), "f"(b));
    return r;
}
__device__ __forceinline__ void ffma2(u64& d, u64 a, u64 b) {
    asm("fma.rn.f32x2 %0, %1, %2, %0;" : "+l"(d) : "l"(a), "l"(b));
}
__device__ __forceinline__ void unpack2(u64 v, float& lo, float& hi) {
    asm("mov.b64 {%0, %1}, %2;" : "=f"(lo), "=f"(hi) : "l"(v));
}

// ---------------------------------------------------------------------------
// Kernel 1: edge scatter. One warp per 4 edges; per edge each lane handles one
// float4 (32 lanes x 16B = 512B = full row, coalesced). All 4 gathers are
// issued before the 4 red.global.add.v4.f32 for MLP=4.
// 800000 edges = 25000 blocks x 8 warps x 4 edges exactly (no bounds checks).
// ---------------------------------------------------------------------------
__global__ void scatter_kernel(const float* __restrict__ feature,
                               const int* __restrict__ edge_src,
                               const int* __restrict__ edge_dst,
                               const float* __restrict__ edge_w) {
    const int wg = (blockIdx.x * blockDim.x + threadIdx.x) >> 5;
    const int lane = threadIdx.x & 31;
    const int e0 = wg * 4;

    int s[4], d[4];
    float w[4];
#pragma unroll
    for (int u = 0; u < 4; u++) {
        s[u] = __ldg(edge_src + e0 + u);
        d[u] = __ldg(edge_dst + e0 + u);
        w[u] = __ldg(edge_w + e0 + u);
    }

    float4 v[4];
#pragma unroll
    for (int u = 0; u < 4; u++) {
        v[u] = reinterpret_cast<const float4*>(feature + (size_t)s[u] * D)[lane];
    }

#pragma unroll
    for (int u = 0; u < 4; u++) {
        const float x = v[u].x * w[u];
        const float y = v[u].y * w[u];
        const float z = v[u].z * w[u];
        const float t = v[u].w * w[u];
        float* dst = g_agg + (size_t)d[u] * D + lane * 4;
        asm volatile("red.global.add.v4.f32 [%0], {%1, %2, %3, %4};"
                     :: "l"(dst), "f"(x), "f"(y), "f"(z), "f"(t)
                     : "memory");
    }
}

// ---------------------------------------------------------------------------
// Kernel 2: out = (feature + agg) @ (0.5*W)  (== (0.5*agg + 0.5*feature) @ W)
//
// 256 threads/block, 16 rows/tile. Thread layout: j = tid&127 (output col),
// half = tid>>7 selects rows 0-7 / 8-15 as 4 float2 row-pairs.
// smem: WsT[j][k] transposed, pitch 132 (conflict-free float4 LDS across j),
//       0.5 factor folded in; pairbuf[p][k] float2 (row 2p, 2p+1 at col k),
//       loaded broadcast (all lanes same addr) as LDS.128.
// Inner loop: per 4 k's: 1 LDS.128 W + 4 packs + per pair (2 LDS.128 +
// 4 fma.rn.f32x2) -> 32 FMAs in 16 FFMA2s. FFMA2 halves fp32 pipe pressure.
// ---------------------------------------------------------------------------
#define WT_PITCH 132

__global__ void gemm_kernel(const float* __restrict__ feature,
                            const float* __restrict__ weight,
                            float* __restrict__ out) {
    extern __shared__ float smem[];
    float* WsT = smem;                          // [128][WT_PITCH]
    float2* pairbuf = reinterpret_cast<float2*>(smem + D * WT_PITCH);  // [8][128]

    const int tid = threadIdx.x;

    // Stage W transposed with 0.5 folded in: WsT[j][k] = 0.5 * W[k][j].
    for (int i = tid; i < D * D; i += 256) {
        const int k = i >> 7;
        const int j = i & 127;
        WsT[j * WT_PITCH + k] = 0.5f * weight[i];
    }
    __syncthreads();

    const int j = tid & 127;
    const int half = tid >> 7;
    const int pbase = half * 4;   // pairs 0-3 (rows 0-7) or 4-7 (rows 8-15)

    for (int r0 = blockIdx.x * 16; r0 < N_NODES; r0 += gridDim.x * 16) {
        // Stage 16 blended rows as float2 pairs: pairbuf[p][k] = (row2p[k], row2p+1[k]).
        {
            const int kk = tid & 127;
            const int pg = (tid >> 7) * 4;
#pragma unroll
            for (int p = pg; p < pg + 4; p++) {
                const int ra = r0 + 2 * p;
                const float a = feature[(size_t)ra * D + kk] + g_agg[(size_t)ra * D + kk];
                const float b = feature[(size_t)(ra + 1) * D + kk] + g_agg[(size_t)(ra + 1) * D + kk];
                pairbuf[p * D + kk] = make_float2(a, b);
            }
        }
        __syncthreads();

        u64 acc0 = pack2(0.f, 0.f), acc1 = acc0, acc2 = acc0, acc3 = acc0;

        const float* wrow = WsT + j * WT_PITCH;
#pragma unroll 4
        for (int k = 0; k < D; k += 4) {
            const float4 wv = *reinterpret_cast<const float4*>(wrow + k);
            const u64 w0 = pack2(wv.x, wv.x);
            const u64 w1 = pack2(wv.y, wv.y);
            const u64 w2 = pack2(wv.z, wv.z);
            const u64 w3 = pack2(wv.w, wv.w);

            const ulonglong2* p0 = reinterpret_cast<const ulonglong2*>(pairbuf + (pbase + 0) * D + k);
            const ulonglong2* p1 = reinterpret_cast<const ulonglong2*>(pairbuf + (pbase + 1) * D + k);
            const ulonglong2* p2 = reinterpret_cast<const ulonglong2*>(pairbuf + (pbase + 2) * D + k);
            const ulonglong2* p3 = reinterpret_cast<const ulonglong2*>(pairbuf + (pbase + 3) * D + k);
            const ulonglong2 a0 = p0[0], b0 = p0[1];
            const ulonglong2 a1 = p1[0], b1 = p1[1];
            const ulonglong2 a2 = p2[0], b2 = p2[1];
            const ulonglong2 a3 = p3[0], b3 = p3[1];

            ffma2(acc0, a0.x, w0); ffma2(acc0, a0.y, w1);
            ffma2(acc0, b0.x, w2); ffma2(acc0, b0.y, w3);
            ffma2(acc1, a1.x, w0); ffma2(acc1, a1.y, w1);
            ffma2(acc1, b1.x, w2); ffma2(acc1, b1.y, w3);
            ffma2(acc2, a2.x, w0); ffma2(acc2, a2.y, w1);
            ffma2(acc2, b2.x, w2); ffma2(acc2, b2.y, w3);
            ffma2(acc3, a3.x, w0); ffma2(acc3, a3.y, w1);
            ffma2(acc3, b3.x, w2); ffma2(acc3, b3.y, w3);
        }

        float lo, hi;
        unpack2(acc0, lo, hi);
        out[(size_t)(r0 + 2 * (pbase + 0) + 0) * D + j] = lo;
        out[(size_t)(r0 + 2 * (pbase + 0) + 1) * D + j] = hi;
        unpack2(acc1, lo, hi);
        out[(size_t)(r0 + 2 * (pbase + 1) + 0) * D + j] = lo;
        out[(size_t)(r0 + 2 * (pbase + 1) + 1) * D + j] = hi;
        unpack2(acc2, lo, hi);
        out[(size_t)(r0 + 2 * (pbase + 2) + 0) * D + j] = lo;
        out[(size_t)(r0 + 2 * (pbase + 2) + 1) * D + j] = hi;
        unpack2(acc3, lo, hi);
        out[(size_t)(r0 + 2 * (pbase + 3) + 0) * D + j] = lo;
        out[(size_t)(r0 + 2 * (pbase + 3) + 1) * D + j] = hi;
        __syncthreads();
    }
}

// ---------------------------------------------------------------------------
extern "C" void kernel_launch(void* const* d_in, const int* in_sizes, int n_in,
                              void* d_out, int out_size) {
    const float* feature  = (const float*)d_in[0];
    const int*   edge_src = (const int*)d_in[1];
    const int*   edge_dst = (const int*)d_in[2];
    const float* edge_w   = (const float*)d_in[3];
    const float* weight   = (const float*)d_in[4];
    float* out = (float*)d_out;

    (void)in_sizes; (void)n_in; (void)out_size;

    const int gemm_smem = (D * WT_PITCH) * (int)sizeof(float) +
                          8 * D * (int)sizeof(float2);

    static float* agg_ptr = nullptr;
    if (!agg_ptr) {
        cudaGetSymbolAddress((void**)&agg_ptr, g_agg);
        cudaFuncSetAttribute(gemm_kernel,
                             cudaFuncAttributeMaxDynamicSharedMemorySize,
                             gemm_smem);
    }

    cudaMemsetAsync(agg_ptr, 0, sizeof(float) * (size_t)N_NODES * D);
    scatter_kernel<<<N_EDGES / 32, 256>>>(feature, edge_src, edge_dst, edge_w);
    gemm_kernel<<<296, 256, gemm_smem>>>(feature, weight, out);
}

// round 5
// speedup vs baseline: 2.0405x; 1.2204x over previous
#include <cuda_runtime.h>
#include <cuda_bf16.h>

#define N_NODES 50000
#define N_EDGES 800000
#define D 128

// Scratch aggregate buffer (no cudaMalloc allowed).
__device__ float g_agg[(size_t)N_NODES * D];

typedef unsigned long long u64;

// ---------------------------------------------------------------------------
// f32x2 packed-FMA helpers (sm_103a; ptxas will not auto-fuse — PTX only).
// ---------------------------------------------------------------------------
__device__ __forceinline__ u64 pack2(float a, float b) {
    u64 r;
    asm("mov.b64 %0, {%1, %2};" : "=l"(r) : "f"(a), "f"(b));
    return r;
}
__device__ __forceinline__ void ffma2(u64& d, u64 a, u64 b) {
    asm("fma.rn.f32x2 %0, %1, %2, %0;" : "+l"(d) : "l"(a), "l"(b));
}
__device__ __forceinline__ void unpack2(u64 v, float& lo, float& hi) {
    asm("mov.b64 {%0, %1}, %2;" : "=f"(lo), "=f"(hi) : "l"(v));
}

// ---------------------------------------------------------------------------
// Kernel 1: edge scatter (unchanged — measured at the LTS throughput wall).
// One warp per 4 edges; per edge each lane handles one float4. MLP=4.
// 800000 = 25000 blocks x 8 warps x 4 edges exactly.
// ---------------------------------------------------------------------------
__global__ void scatter_kernel(const float* __restrict__ feature,
                               const int* __restrict__ edge_src,
                               const int* __restrict__ edge_dst,
                               const float* __restrict__ edge_w) {
    const int wg = (blockIdx.x * blockDim.x + threadIdx.x) >> 5;
    const int lane = threadIdx.x & 31;
    const int e0 = wg * 4;

    int s[4], d[4];
    float w[4];
#pragma unroll
    for (int u = 0; u < 4; u++) {
        s[u] = __ldg(edge_src + e0 + u);
        d[u] = __ldg(edge_dst + e0 + u);
        w[u] = __ldg(edge_w + e0 + u);
    }

    float4 v[4];
#pragma unroll
    for (int u = 0; u < 4; u++) {
        v[u] = reinterpret_cast<const float4*>(feature + (size_t)s[u] * D)[lane];
    }

#pragma unroll
    for (int u = 0; u < 4; u++) {
        const float x = v[u].x * w[u];
        const float y = v[u].y * w[u];
        const float z = v[u].z * w[u];
        const float t = v[u].w * w[u];
        float* dst = g_agg + (size_t)d[u] * D + lane * 4;
        asm volatile("red.global.add.v4.f32 [%0], {%1, %2, %3, %4};"
                     :: "l"(dst), "f"(x), "f"(y), "f"(z), "f"(t)
                     : "memory");
    }
}

// ---------------------------------------------------------------------------
// Kernel 2: out = (feature + agg) @ (0.5*W)
//
// Block: 256 threads, tile = 32 rows x 128 cols.
// Thread: jp = tid&63 -> cols (2jp, 2jp+1); rq = tid>>6 -> rows rq*8..rq*8+7
//         (= row-pairs rq*4..rq*4+3).
// Accumulators pack ROW-PAIRS: acc[p][c] = (out[2p][j+c], out[2p+1][j+c]).
// smem:
//   Wp[jp][k]  float2 = 0.5*(W[k][2jp], W[k][2jp+1]), k-pitch 130
//              (row stride 260 words == 4 mod 128 -> conflict-free 16B loads
//              across 32 lanes with distinct jp).
//   pairbuf[p][k] float2 = (row(2p)[k], row(2p+1)[k]) — warp-broadcast loads.
// Per 4-k chunk / thread: 2 W LDS.128 + 8 row LDS.128 + 8 w-dup packs +
// 32 fma.rn.f32x2  => 64 FMAs / 10 LDS (vs 3.6 before).
// ---------------------------------------------------------------------------
#define WP_PITCH 130  // float2 units

__global__ void __launch_bounds__(256, 2)
gemm_kernel(const float* __restrict__ feature,
            const float* __restrict__ weight,
            float* __restrict__ out) {
    extern __shared__ float2 smem2[];
    float2* Wp = smem2;                          // [64][WP_PITCH]
    float2* pairbuf = smem2 + 64 * WP_PITCH;     // [16][128]

    const int tid = threadIdx.x;

    // Stage Wp[jp][k] = 0.5 * (W[k][2jp], W[k][2jp+1]) via float2 reads.
    {
        const float2* wf2 = reinterpret_cast<const float2*>(weight);
        for (int i = tid; i < D * 64; i += 256) {
            const int k = i >> 6;
            const int jp = i & 63;
            float2 v = wf2[i];
            Wp[jp * WP_PITCH + k] = make_float2(0.5f * v.x, 0.5f * v.y);
        }
    }
    __syncthreads();

    const int jp = tid & 63;
    const int j = jp * 2;
    const int rq = tid >> 6;
    const int pbase = rq * 4;           // row-pairs pbase..pbase+3

    const float2* ff2 = reinterpret_cast<const float2*>(feature);
    const float2* gg2 = reinterpret_cast<const float2*>(g_agg);

    const int n_tiles = (N_NODES + 31) / 32;   // 1563

    for (int t = blockIdx.x; t < n_tiles; t += gridDim.x) {
        const int r0 = t * 32;

        // Stage 32 rows as 16 interleaved row-pairs.
        for (int idx = tid; idx < 16 * 64; idx += 256) {
            const int p = idx >> 6;
            const int kk2 = idx & 63;
            const int ra = r0 + 2 * p;
            float2 A = make_float2(0.f, 0.f), B = A;
            if (ra + 1 < N_NODES) {
                float2 fa = ff2[(size_t)ra * 64 + kk2];
                float2 ga = gg2[(size_t)ra * 64 + kk2];
                float2 fb = ff2[(size_t)(ra + 1) * 64 + kk2];
                float2 gb = gg2[(size_t)(ra + 1) * 64 + kk2];
                A = make_float2(fa.x + ga.x, fa.y + ga.y);
                B = make_float2(fb.x + gb.x, fb.y + gb.y);
            } else if (ra < N_NODES) {
                float2 fa = ff2[(size_t)ra * 64 + kk2];
                float2 ga = gg2[(size_t)ra * 64 + kk2];
                A = make_float2(fa.x + ga.x, fa.y + ga.y);
            }
            pairbuf[p * D + 2 * kk2 + 0] = make_float2(A.x, B.x);
            pairbuf[p * D + 2 * kk2 + 1] = make_float2(A.y, B.y);
        }
        __syncthreads();

        u64 acc[4][2];
#pragma unroll
        for (int p = 0; p < 4; p++) {
            acc[p][0] = pack2(0.f, 0.f);
            acc[p][1] = pack2(0.f, 0.f);
        }

        const ulonglong2* wrow =
            reinterpret_cast<const ulonglong2*>(Wp + jp * WP_PITCH);

#pragma unroll 2
        for (int k = 0; k < D; k += 4) {
            // W for cols (j, j+1) at k..k+3.
            const ulonglong2 wA = wrow[(k >> 1) + 0];   // k, k+1
            const ulonglong2 wB = wrow[(k >> 1) + 1];   // k+2, k+3
            float w0a, w0b, w1a, w1b, w2a, w2b, w3a, w3b;
            unpack2(wA.x, w0a, w0b);
            unpack2(wA.y, w1a, w1b);
            unpack2(wB.x, w2a, w2b);
            unpack2(wB.y, w3a, w3b);
            const u64 d00 = pack2(w0a, w0a), d01 = pack2(w0b, w0b);
            const u64 d10 = pack2(w1a, w1a), d11 = pack2(w1b, w1b);
            const u64 d20 = pack2(w2a, w2a), d21 = pack2(w2b, w2b);
            const u64 d30 = pack2(w3a, w3a), d31 = pack2(w3b, w3b);

#pragma unroll
            for (int p = 0; p < 4; p++) {
                const ulonglong2* rp = reinterpret_cast<const ulonglong2*>(
                    pairbuf + (pbase + p) * D + k);
                const ulonglong2 a = rp[0];   // k, k+1
                const ulonglong2 b = rp[1];   // k+2, k+3
                ffma2(acc[p][0], a.x, d00);
                ffma2(acc[p][0], a.y, d10);
                ffma2(acc[p][0], b.x, d20);
                ffma2(acc[p][0], b.y, d30);
                ffma2(acc[p][1], a.x, d01);
                ffma2(acc[p][1], a.y, d11);
                ffma2(acc[p][1], b.x, d21);
                ffma2(acc[p][1], b.y, d31);
            }
        }

        // Store: per pair, rows (2p, 2p+1), cols (j, j+1) as float2 each.
#pragma unroll
        for (int p = 0; p < 4; p++) {
            float c0lo, c0hi, c1lo, c1hi;
            unpack2(acc[p][0], c0lo, c0hi);
            unpack2(acc[p][1], c1lo, c1hi);
            const int ra = r0 + 2 * (pbase + p);
            if (ra < N_NODES) {
                reinterpret_cast<float2*>(out + (size_t)ra * D + j)[0] =
                    make_float2(c0lo, c1lo);
            }
            if (ra + 1 < N_NODES) {
                reinterpret_cast<float2*>(out + (size_t)(ra + 1) * D + j)[0] =
                    make_float2(c0hi, c1hi);
            }
        }
        __syncthreads();
    }
}

// ---------------------------------------------------------------------------
extern "C" void kernel_launch(void* const* d_in, const int* in_sizes, int n_in,
                              void* d_out, int out_size) {
    const float* feature  = (const float*)d_in[0];
    const int*   edge_src = (const int*)d_in[1];
    const int*   edge_dst = (const int*)d_in[2];
    const float* edge_w   = (const float*)d_in[3];
    const float* weight   = (const float*)d_in[4];
    float* out = (float*)d_out;

    (void)in_sizes; (void)n_in; (void)out_size;

    const int gemm_smem = (64 * WP_PITCH + 16 * D) * (int)sizeof(float2);

    static float* agg_ptr = nullptr;
    if (!agg_ptr) {
        cudaGetSymbolAddress((void**)&agg_ptr, g_agg);
        cudaFuncSetAttribute(gemm_kernel,
                             cudaFuncAttributeMaxDynamicSharedMemorySize,
                             gemm_smem);
    }

    cudaMemsetAsync(agg_ptr, 0, sizeof(float) * (size_t)N_NODES * D);
    scatter_kernel<<<N_EDGES / 32, 256>>>(feature, edge_src, edge_dst, edge_w);
    gemm_kernel<<<296, 256, gemm_smem>>>(feature, weight, out);
}

// round 7
// speedup vs baseline: 2.0705x; 1.0147x over previous
#include <cuda_runtime.h>
#include <cuda_bf16.h>

#define N_NODES 50000
#define N_EDGES 800000
#define D 128

// Scratch: holds P = feature @ W (no cudaMalloc allowed).
__device__ float g_P[(size_t)N_NODES * D];

typedef unsigned long long u64;

// ---------------------------------------------------------------------------
// f32x2 packed-FMA helpers (PTX-only; ptxas won't auto-fuse).
// ---------------------------------------------------------------------------
__device__ __forceinline__ u64 pack2(float a, float b) {
    u64 r;
    asm("mov.b64 %0, {%1, %2};" : "=l"(r) : "f"(a), "f"(b));
    return r;
}
__device__ __forceinline__ void ffma2(u64& d, u64 a, u64 b) {
    asm("fma.rn.f32x2 %0, %1, %2, %0;" : "+l"(d) : "l"(a), "l"(b));
}
__device__ __forceinline__ void unpack2(u64 v, float& lo, float& hi) {
    asm("mov.b64 {%0, %1}, %2;" : "=f"(lo), "=f"(hi) : "l"(v));
}

// ---------------------------------------------------------------------------
// Kernel 1: P = feature @ W, and out = 0.5*P (initializes d_out; REDG scatter
// accumulates on top afterwards -> no memset pass needed).
//
// Block: 256 threads, tile = 64 rows x 128 cols (782 tiles, persistent grid).
// Thread: jq = tid&31 -> col quad (4jq..4jq+3); rq = tid>>5 -> row pairs
//         rq*4..rq*4+3 (rows rq*8..rq*8+7).
// smem:
//   Wq[jq][k] float4 = W[k][4jq..4jq+3], k-pitch 129 float4 (lane stride
//     516 words == 4 mod 32 banks -> conflict-free LDS.128 across lanes).
//   pairbuf[p][k] float2 = (row(2p)[k], row(2p+1)[k]) — within a warp all
//     lanes share rq -> pure broadcast loads (1 wavefront each).
// Per 4-k chunk / thread: 4 W LDS.128 (16 wf) + 8 row LDS.128 (8 wf broadcast)
// vs 64 FFMA2 (32 fma-cyc) -> crossbar/fma ratio 0.75 (was 1.0).
// ---------------------------------------------------------------------------
#define WQ_PITCH 129  // float4 units

__global__ void __launch_bounds__(256, 2)
gemm_kernel(const float* __restrict__ feature,
            const float* __restrict__ weight,
            float* __restrict__ Pbuf,
            float* __restrict__ out) {
    extern __shared__ float4 smem4[];
    float4* Wq = smem4;                                     // [32][WQ_PITCH]
    float2* pairbuf = reinterpret_cast<float2*>(smem4 + 32 * WQ_PITCH); // [32][128]

    const int tid = threadIdx.x;

    // Stage Wq[jq][k] = W[k][4jq..4jq+3].
    {
        const float4* wf4 = reinterpret_cast<const float4*>(weight); // [128][32]
        for (int i = tid; i < 128 * 32; i += 256) {
            const int k = i >> 5;
            const int jq = i & 31;
            Wq[jq * WQ_PITCH + k] = wf4[i];
        }
    }
    __syncthreads();

    const int jq = tid & 31;
    const int j = jq * 4;
    const int rq = tid >> 5;        // 0..7
    const int pbase = rq * 4;       // row-pairs pbase..pbase+3

    const float2* ff2 = reinterpret_cast<const float2*>(feature);

    const int n_tiles = (N_NODES + 63) / 64;   // 782

    for (int t = blockIdx.x; t < n_tiles; t += gridDim.x) {
        const int r0 = t * 64;

        // Stage 64 rows as 32 interleaved row-pairs.
        for (int idx = tid; idx < 32 * 64; idx += 256) {
            const int p = idx >> 6;
            const int kk2 = idx & 63;
            const int ra = r0 + 2 * p;
            float2 A = make_float2(0.f, 0.f), B = A;
            if (ra + 1 < N_NODES) {
                A = ff2[(size_t)ra * 64 + kk2];
                B = ff2[(size_t)(ra + 1) * 64 + kk2];
            } else if (ra < N_NODES) {
                A = ff2[(size_t)ra * 64 + kk2];
            }
            pairbuf[p * D + 2 * kk2 + 0] = make_float2(A.x, B.x);
            pairbuf[p * D + 2 * kk2 + 1] = make_float2(A.y, B.y);
        }
        __syncthreads();

        u64 acc[4][4];  // [pair][col]
#pragma unroll
        for (int p = 0; p < 4; p++)
#pragma unroll
            for (int c = 0; c < 4; c++)
                acc[p][c] = pack2(0.f, 0.f);

        const float4* wrow = Wq + jq * WQ_PITCH;

#pragma unroll 2
        for (int k = 0; k < D; k += 4) {
            const float4 w0 = wrow[k + 0];
            const float4 w1 = wrow[k + 1];
            const float4 w2 = wrow[k + 2];
            const float4 w3 = wrow[k + 3];

            u64 d0[4], d1[4], d2[4], d3[4];
            d0[0] = pack2(w0.x, w0.x); d0[1] = pack2(w0.y, w0.y);
            d0[2] = pack2(w0.z, w0.z); d0[3] = pack2(w0.w, w0.w);
            d1[0] = pack2(w1.x, w1.x); d1[1] = pack2(w1.y, w1.y);
            d1[2] = pack2(w1.z, w1.z); d1[3] = pack2(w1.w, w1.w);
            d2[0] = pack2(w2.x, w2.x); d2[1] = pack2(w2.y, w2.y);
            d2[2] = pack2(w2.z, w2.z); d2[3] = pack2(w2.w, w2.w);
            d3[0] = pack2(w3.x, w3.x); d3[1] = pack2(w3.y, w3.y);
            d3[2] = pack2(w3.z, w3.z); d3[3] = pack2(w3.w, w3.w);

#pragma unroll
            for (int p = 0; p < 4; p++) {
                const ulonglong2* rp = reinterpret_cast<const ulonglong2*>(
                    pairbuf + (pbase + p) * D + k);
                const ulonglong2 a = rp[0];   // k, k+1
                const ulonglong2 b = rp[1];   // k+2, k+3
#pragma unroll
                for (int c = 0; c < 4; c++) {
                    ffma2(acc[p][c], a.x, d0[c]);
                    ffma2(acc[p][c], a.y, d1[c]);
                    ffma2(acc[p][c], b.x, d2[c]);
                    ffma2(acc[p][c], b.y, d3[c]);
                }
            }
        }

        // Epilogue: per pair write rows (2p, 2p+1): P (full) and out (0.5x).
#pragma unroll
        for (int p = 0; p < 4; p++) {
            float lo[4], hi[4];
#pragma unroll
            for (int c = 0; c < 4; c++) unpack2(acc[p][c], lo[c], hi[c]);
            const int ra = r0 + 2 * (pbase + p);
            if (ra < N_NODES) {
                const float4 v = make_float4(lo[0], lo[1], lo[2], lo[3]);
                *reinterpret_cast<float4*>(Pbuf + (size_t)ra * D + j) = v;
                *reinterpret_cast<float4*>(out + (size_t)ra * D + j) =
                    make_float4(0.5f * v.x, 0.5f * v.y, 0.5f * v.z, 0.5f * v.w);
            }
            if (ra + 1 < N_NODES) {
                const float4 v = make_float4(hi[0], hi[1], hi[2], hi[3]);
                *reinterpret_cast<float4*>(Pbuf + (size_t)(ra + 1) * D + j) = v;
                *reinterpret_cast<float4*>(out + (size_t)(ra + 1) * D + j) =
                    make_float4(0.5f * v.x, 0.5f * v.y, 0.5f * v.z, 0.5f * v.w);
            }
        }
        __syncthreads();
    }
}

// ---------------------------------------------------------------------------
// Kernel 2: edge scatter in projected space: out[dst] += (0.5*w) * P[src].
// One warp per 4 edges; per edge each lane handles one float4. MLP=4.
// P is L2-hot (just written). 800000 = 25000 blocks x 8 warps x 4 edges.
// ---------------------------------------------------------------------------
__global__ void scatter_kernel(const float* __restrict__ P,
                               const int* __restrict__ edge_src,
                               const int* __restrict__ edge_dst,
                               const float* __restrict__ edge_w,
                               float* __restrict__ out) {
    const int wg = (blockIdx.x * blockDim.x + threadIdx.x) >> 5;
    const int lane = threadIdx.x & 31;
    const int e0 = wg * 4;

    int s[4], d[4];
    float w[4];
#pragma unroll
    for (int u = 0; u < 4; u++) {
        s[u] = __ldg(edge_src + e0 + u);
        d[u] = __ldg(edge_dst + e0 + u);
        w[u] = 0.5f * __ldg(edge_w + e0 + u);
    }

    float4 v[4];
#pragma unroll
    for (int u = 0; u < 4; u++) {
        v[u] = reinterpret_cast<const float4*>(P + (size_t)s[u] * D)[lane];
    }

#pragma unroll
    for (int u = 0; u < 4; u++) {
        const float x = v[u].x * w[u];
        const float y = v[u].y * w[u];
        const float z = v[u].z * w[u];
        const float t = v[u].w * w[u];
        float* dst = out + (size_t)d[u] * D + lane * 4;
        asm volatile("red.global.add.v4.f32 [%0], {%1, %2, %3, %4};"
                     :: "l"(dst), "f"(x), "f"(y), "f"(z), "f"(t)
                     : "memory");
    }
}

// ---------------------------------------------------------------------------
extern "C" void kernel_launch(void* const* d_in, const int* in_sizes, int n_in,
                              void* d_out, int out_size) {
    const float* feature  = (const float*)d_in[0];
    const int*   edge_src = (const int*)d_in[1];
    const int*   edge_dst = (const int*)d_in[2];
    const float* edge_w   = (const float*)d_in[3];
    const float* weight   = (const float*)d_in[4];
    float* out = (float*)d_out;

    (void)in_sizes; (void)n_in; (void)out_size;

    const int gemm_smem = 32 * WQ_PITCH * (int)sizeof(float4) +
                          32 * D * (int)sizeof(float2);

    static float* P_ptr = nullptr;
    if (!P_ptr) {
        cudaGetSymbolAddress((void**)&P_ptr, g_P);
        cudaFuncSetAttribute(gemm_kernel,
                             cudaFuncAttributeMaxDynamicSharedMemorySize,
                             gemm_smem);
    }

    gemm_kernel<<<296, 256, gemm_smem>>>(feature, weight, P_ptr, out);
    scatter_kernel<<<N_EDGES / 32, 256>>>(P_ptr, edge_src, edge_dst, edge_w,
                                          out);
}

// round 8
// speedup vs baseline: 2.6244x; 1.2675x over previous
#include <cuda_runtime.h>
#include <cuda_bf16.h>

#define N_NODES 50000
#define N_EDGES 800000
#define D 128
#define MAX_SLOTS 64

// Scratch (no cudaMalloc allowed).
__device__ float g_P[(size_t)N_NODES * D];                       // P = feature @ W
__device__ unsigned long long g_slots[(size_t)N_NODES * MAX_SLOTS]; // packed (src, 0.5w)
__device__ int g_cursor[N_NODES];

typedef unsigned long long u64;

// ---------------------------------------------------------------------------
// f32x2 packed-FMA helpers (PTX-only; ptxas won't auto-fuse).
// ---------------------------------------------------------------------------
__device__ __forceinline__ u64 pack2(float a, float b) {
    u64 r;
    asm("mov.b64 %0, {%1, %2};" : "=l"(r) : "f"(a), "f"(b));
    return r;
}
__device__ __forceinline__ void ffma2(u64& d, u64 a, u64 b) {
    asm("fma.rn.f32x2 %0, %1, %2, %0;" : "+l"(d) : "l"(a), "l"(b));
}
__device__ __forceinline__ void unpack2(u64 v, float& lo, float& hi) {
    asm("mov.b64 {%0, %1}, %2;" : "=f"(lo), "=f"(hi) : "l"(v));
}

// ---------------------------------------------------------------------------
// Kernel 1: P = feature @ W and out = 0.5*P (unchanged from round 5/7 —
// measured 44 us; fma-balanced 8rx4c f32x2 tile).
// ---------------------------------------------------------------------------
#define WQ_PITCH 129  // float4 units

__global__ void __launch_bounds__(256, 2)
gemm_kernel(const float* __restrict__ feature,
            const float* __restrict__ weight,
            float* __restrict__ Pbuf,
            float* __restrict__ out) {
    extern __shared__ float4 smem4[];
    float4* Wq = smem4;                                     // [32][WQ_PITCH]
    float2* pairbuf = reinterpret_cast<float2*>(smem4 + 32 * WQ_PITCH); // [32][128]

    const int tid = threadIdx.x;

    {
        const float4* wf4 = reinterpret_cast<const float4*>(weight); // [128][32]
        for (int i = tid; i < 128 * 32; i += 256) {
            const int k = i >> 5;
            const int jq = i & 31;
            Wq[jq * WQ_PITCH + k] = wf4[i];
        }
    }
    __syncthreads();

    const int jq = tid & 31;
    const int j = jq * 4;
    const int rq = tid >> 5;
    const int pbase = rq * 4;

    const float2* ff2 = reinterpret_cast<const float2*>(feature);
    const int n_tiles = (N_NODES + 63) / 64;   // 782

    for (int t = blockIdx.x; t < n_tiles; t += gridDim.x) {
        const int r0 = t * 64;

        for (int idx = tid; idx < 32 * 64; idx += 256) {
            const int p = idx >> 6;
            const int kk2 = idx & 63;
            const int ra = r0 + 2 * p;
            float2 A = make_float2(0.f, 0.f), B = A;
            if (ra + 1 < N_NODES) {
                A = ff2[(size_t)ra * 64 + kk2];
                B = ff2[(size_t)(ra + 1) * 64 + kk2];
            } else if (ra < N_NODES) {
                A = ff2[(size_t)ra * 64 + kk2];
            }
            pairbuf[p * D + 2 * kk2 + 0] = make_float2(A.x, B.x);
            pairbuf[p * D + 2 * kk2 + 1] = make_float2(A.y, B.y);
        }
        __syncthreads();

        u64 acc[4][4];
#pragma unroll
        for (int p = 0; p < 4; p++)
#pragma unroll
            for (int c = 0; c < 4; c++)
                acc[p][c] = pack2(0.f, 0.f);

        const float4* wrow = Wq + jq * WQ_PITCH;

#pragma unroll 2
        for (int k = 0; k < D; k += 4) {
            const float4 w0 = wrow[k + 0];
            const float4 w1 = wrow[k + 1];
            const float4 w2 = wrow[k + 2];
            const float4 w3 = wrow[k + 3];

            u64 d0[4], d1[4], d2[4], d3[4];
            d0[0] = pack2(w0.x, w0.x); d0[1] = pack2(w0.y, w0.y);
            d0[2] = pack2(w0.z, w0.z); d0[3] = pack2(w0.w, w0.w);
            d1[0] = pack2(w1.x, w1.x); d1[1] = pack2(w1.y, w1.y);
            d1[2] = pack2(w1.z, w1.z); d1[3] = pack2(w1.w, w1.w);
            d2[0] = pack2(w2.x, w2.x); d2[1] = pack2(w2.y, w2.y);
            d2[2] = pack2(w2.z, w2.z); d2[3] = pack2(w2.w, w2.w);
            d3[0] = pack2(w3.x, w3.x); d3[1] = pack2(w3.y, w3.y);
            d3[2] = pack2(w3.z, w3.z); d3[3] = pack2(w3.w, w3.w);

#pragma unroll
            for (int p = 0; p < 4; p++) {
                const ulonglong2* rp = reinterpret_cast<const ulonglong2*>(
                    pairbuf + (pbase + p) * D + k);
                const ulonglong2 a = rp[0];
                const ulonglong2 b = rp[1];
#pragma unroll
                for (int c = 0; c < 4; c++) {
                    ffma2(acc[p][c], a.x, d0[c]);
                    ffma2(acc[p][c], a.y, d1[c]);
                    ffma2(acc[p][c], b.x, d2[c]);
                    ffma2(acc[p][c], b.y, d3[c]);
                }
            }
        }

#pragma unroll
        for (int p = 0; p < 4; p++) {
            float lo[4], hi[4];
#pragma unroll
            for (int c = 0; c < 4; c++) unpack2(acc[p][c], lo[c], hi[c]);
            const int ra = r0 + 2 * (pbase + p);
            if (ra < N_NODES) {
                const float4 v = make_float4(lo[0], lo[1], lo[2], lo[3]);
                *reinterpret_cast<float4*>(Pbuf + (size_t)ra * D + j) = v;
                *reinterpret_cast<float4*>(out + (size_t)ra * D + j) =
                    make_float4(0.5f * v.x, 0.5f * v.y, 0.5f * v.z, 0.5f * v.w);
            }
            if (ra + 1 < N_NODES) {
                const float4 v = make_float4(hi[0], hi[1], hi[2], hi[3]);
                *reinterpret_cast<float4*>(Pbuf + (size_t)(ra + 1) * D + j) = v;
                *reinterpret_cast<float4*>(out + (size_t)(ra + 1) * D + j) =
                    make_float4(0.5f * v.x, 0.5f * v.y, 0.5f * v.z, 0.5f * v.w);
            }
        }
        __syncthreads();
    }
}

// ---------------------------------------------------------------------------
// Kernel 2: bin edges by dst. One thread per edge. pos = atomicAdd(cursor).
// Packed record: low 32 = src, high 32 = 0.5*w. Overflow (>MAX_SLOTS, which
// never fires for Poisson(16) degrees) falls back to direct REDG into out
// (out already holds 0.5*P — all contributions additive).
// ---------------------------------------------------------------------------
__global__ void bin_kernel(const int* __restrict__ edge_src,
                           const int* __restrict__ edge_dst,
                           const float* __restrict__ edge_w,
                           const float* __restrict__ P,
                           float* __restrict__ out) {
    const int e = blockIdx.x * blockDim.x + threadIdx.x;
    if (e >= N_EDGES) return;
    const int s = edge_src[e];
    const int d = edge_dst[e];
    const float hw = 0.5f * edge_w[e];
    const int pos = atomicAdd(&g_cursor[d], 1);
    if (pos < MAX_SLOTS) {
        const u64 rec = ((u64)__float_as_uint(hw) << 32) | (unsigned)s;
        g_slots[(size_t)d * MAX_SLOTS + pos] = rec;
    } else {
        // Rare fallback: scalar REDG of the whole row by this thread.
        const float4* src4 = reinterpret_cast<const float4*>(P + (size_t)s * D);
        float* dp = out + (size_t)d * D;
#pragma unroll 4
        for (int q = 0; q < 32; q++) {
            const float4 v = src4[q];
            asm volatile("red.global.add.v4.f32 [%0], {%1, %2, %3, %4};"
                         :: "l"(dp + 4 * q),
                            "f"(v.x * hw), "f"(v.y * hw), "f"(v.z * hw), "f"(v.w * hw)
                         : "memory");
        }
    }
}

// ---------------------------------------------------------------------------
// Kernel 3: per-dst gather. One warp per node (50000 = 6250 blocks x 8 warps).
// Broadcast-read slot records, gather P[src] float4/lane with MLP=4,
// accumulate in registers, single red.global.add.v4 per node at the end
// (25.6 MB RMW total instead of 410 MB).
// ---------------------------------------------------------------------------
__global__ void __launch_bounds__(256)
gather_kernel(const float* __restrict__ P,
              float* __restrict__ out) {
    const int dst = (blockIdx.x * blockDim.x + threadIdx.x) >> 5;
    const int lane = threadIdx.x & 31;

    const int cnt = min(g_cursor[dst], MAX_SLOTS);
    const u64* row = g_slots + (size_t)dst * MAX_SLOTS;

    float ax = 0.f, ay = 0.f, az = 0.f, aw = 0.f;

    int e = 0;
    for (; e + 4 <= cnt; e += 4) {
        const u64 r0 = row[e + 0];
        const u64 r1 = row[e + 1];
        const u64 r2 = row[e + 2];
        const u64 r3 = row[e + 3];
        const int s0 = (int)(unsigned)r0;
        const int s1 = (int)(unsigned)r1;
        const int s2 = (int)(unsigned)r2;
        const int s3 = (int)(unsigned)r3;
        const float w0 = __uint_as_float((unsigned)(r0 >> 32));
        const float w1 = __uint_as_float((unsigned)(r1 >> 32));
        const float w2 = __uint_as_float((unsigned)(r2 >> 32));
        const float w3 = __uint_as_float((unsigned)(r3 >> 32));

        const float4 v0 = reinterpret_cast<const float4*>(P + (size_t)s0 * D)[lane];
        const float4 v1 = reinterpret_cast<const float4*>(P + (size_t)s1 * D)[lane];
        const float4 v2 = reinterpret_cast<const float4*>(P + (size_t)s2 * D)[lane];
        const float4 v3 = reinterpret_cast<const float4*>(P + (size_t)s3 * D)[lane];

        ax += v0.x * w0; ay += v0.y * w0; az += v0.z * w0; aw += v0.w * w0;
        ax += v1.x * w1; ay += v1.y * w1; az += v1.z * w1; aw += v1.w * w1;
        ax += v2.x * w2; ay += v2.y * w2; az += v2.z * w2; aw += v2.w * w2;
        ax += v3.x * w3; ay += v3.y * w3; az += v3.z * w3; aw += v3.w * w3;
    }
    for (; e < cnt; e++) {
        const u64 r = row[e];
        const int s = (int)(unsigned)r;
        const float w = __uint_as_float((unsigned)(r >> 32));
        const float4 v = reinterpret_cast<const float4*>(P + (size_t)s * D)[lane];
        ax += v.x * w; ay += v.y * w; az += v.z * w; aw += v.w * w;
    }

    if (cnt > 0) {
        float* dp = out + (size_t)dst * D + lane * 4;
        asm volatile("red.global.add.v4.f32 [%0], {%1, %2, %3, %4};"
                     :: "l"(dp), "f"(ax), "f"(ay), "f"(az), "f"(aw)
                     : "memory");
    }
}

// ---------------------------------------------------------------------------
extern "C" void kernel_launch(void* const* d_in, const int* in_sizes, int n_in,
                              void* d_out, int out_size) {
    const float* feature  = (const float*)d_in[0];
    const int*   edge_src = (const int*)d_in[1];
    const int*   edge_dst = (const int*)d_in[2];
    const float* edge_w   = (const float*)d_in[3];
    const float* weight   = (const float*)d_in[4];
    float* out = (float*)d_out;

    (void)in_sizes; (void)n_in; (void)out_size;

    const int gemm_smem = 32 * WQ_PITCH * (int)sizeof(float4) +
                          32 * D * (int)sizeof(float2);

    static float* P_ptr = nullptr;
    static int* cursor_ptr = nullptr;
    if (!P_ptr) {
        cudaGetSymbolAddress((void**)&P_ptr, g_P);
        cudaGetSymbolAddress((void**)&cursor_ptr, g_cursor);
        cudaFuncSetAttribute(gemm_kernel,
                             cudaFuncAttributeMaxDynamicSharedMemorySize,
                             gemm_smem);
    }

    cudaMemsetAsync(cursor_ptr, 0, sizeof(int) * N_NODES);
    gemm_kernel<<<296, 256, gemm_smem>>>(feature, weight, P_ptr, out);
    bin_kernel<<<(N_EDGES + 255) / 256, 256>>>(edge_src, edge_dst, edge_w,
                                               P_ptr, out);
    gather_kernel<<<N_NODES / 8, 256>>>(P_ptr, out);
}